// round 8
// baseline (speedup 1.0000x reference)
#include <cuda_runtime.h>
#include <cuda_bf16.h>
#include <cstdint>
#include <math.h>

#define HW 4096
#define A_POS (4 * 66)              // halo positions per chunk tile (4 rows x 66 cols)
#define A_ROW_B 128                 // 32ch hi (64B) + 32ch lo (64B), SW128 swizzled
#define A_BUF_B (A_POS * A_ROW_B)   // 33792 B per A buffer
#define B_SLOT_B (128 * 128)        // 16384 B per B slot (<=128 n rows x 128B)
#define SMEM_BYTES (2 * A_BUF_B + 2 * B_SLOT_B)   // 100352 B -> 2 CTAs/SM

// ---------------- device scratch ----------------
__device__ __nv_bfloat16 g_q_hi   [4u * 4096u * 768u];
__device__ __nv_bfloat16 g_q_lo   [4u * 4096u * 768u];
__device__ __nv_bfloat16 g_flat_hi[12u * 4096u * 256u];
__device__ __nv_bfloat16 g_flat_lo[12u * 4096u * 256u];
__device__ __nv_bfloat16 g_samp_hi[4u * 4096u * 256u];
__device__ __nv_bfloat16 g_samp_lo[4u * 4096u * 256u];
__device__ float g_value_t[12u * 4096u * 256u];
__device__ float g_oa_t   [4u * 4096u * 288u];        // merged off(0:192)+attn(192:288), token-major
__device__ float g_boa    [288];
__device__ __nv_bfloat16 g_wv_hi [9u * 256u * 256u], g_wv_lo [9u * 256u * 256u];
__device__ __nv_bfloat16 g_woa_hi[9u * 288u * 768u], g_woa_lo[9u * 288u * 768u];
__device__ __nv_bfloat16 g_wu_hi [9u * 256u * 256u], g_wu_lo [9u * 256u * 256u];

// ---------------- helpers ----------------
__device__ __forceinline__ void mma16816(float* c, const unsigned* a, unsigned b0, unsigned b1)
{
    asm volatile("mma.sync.aligned.m16n8k16.row.col.f32.bf16.bf16.f32 "
        "{%0,%1,%2,%3}, {%4,%5,%6,%7}, {%8,%9}, {%0,%1,%2,%3};"
        : "+f"(c[0]), "+f"(c[1]), "+f"(c[2]), "+f"(c[3])
        : "r"(a[0]), "r"(a[1]), "r"(a[2]), "r"(a[3]), "r"(b0), "r"(b1));
}

__device__ __forceinline__ void cp16(unsigned daddr, const void* src, int srcsz)
{
    asm volatile("cp.async.cg.shared.global [%0], [%1], 16, %2;\n"
                 :: "r"(daddr), "l"(src), "r"(srcsz));
}

__device__ __forceinline__ void ldsm4(unsigned* d, unsigned saddr)
{
    asm volatile("ldmatrix.sync.aligned.m8n8.x4.shared.b16 {%0,%1,%2,%3}, [%4];"
        : "=r"(d[0]), "=r"(d[1]), "=r"(d[2]), "=r"(d[3]) : "r"(saddr));
}

// ---------------- conversion kernels ----------------
__global__ void chlast_split(const float* __restrict__ in, __nv_bfloat16* __restrict__ hi,
                             __nv_bfloat16* __restrict__ lo, int C)
{
    __shared__ float t[32][33];
    int img = blockIdx.z;
    int p0 = blockIdx.x * 32, c0 = blockIdx.y * 32;
    int tx = threadIdx.x;
    for (int j = threadIdx.y; j < 32; j += 8)
        t[j][tx] = in[((size_t)img * C + c0 + j) * HW + p0 + tx];
    __syncthreads();
    for (int j = threadIdx.y; j < 32; j += 8) {
        float v = t[tx][j];
        __nv_bfloat16 h = __float2bfloat16(v);
        size_t o = ((size_t)img * HW + p0 + j) * C + c0 + tx;
        hi[o] = h;
        lo[o] = __float2bfloat16(v - __bfloat162float(h));
    }
}

// put one weight element: w[co][ci][3][3] -> buf[tap][co_off+co][ci]
__device__ __forceinline__ void wput(const float* __restrict__ w, __nv_bfloat16* hi,
                                     __nv_bfloat16* lo, int i, int cout, int cin,
                                     int co_off, int cout_buf)
{
    int ci = i % cin; int r = i / cin; int co = r % cout; int tap = r / cout;
    float v = w[((size_t)co * cin + ci) * 9 + tap];
    __nv_bfloat16 h = __float2bfloat16(v);
    size_t o = ((size_t)tap * cout_buf + co_off + co) * cin + ci;
    hi[o] = h;
    lo[o] = __float2bfloat16(v - __bfloat162float(h));
}

#define WN0 (9 * 256 * 256)
#define WN1 (9 * 192 * 768)
#define WN2 (9 * 96  * 768)
#define WN3 (9 * 256 * 256)
__global__ void wprep(const float* __restrict__ wv, const float* __restrict__ wo,
                      const float* __restrict__ wa, const float* __restrict__ wu,
                      const float* __restrict__ bo, const float* __restrict__ ba)
{
    int i = blockIdx.x * 256 + threadIdx.x;
    if (i < WN0) {
        wput(wv, g_wv_hi, g_wv_lo, i, 256, 256, 0, 256);
    } else if (i < WN0 + WN1) {
        wput(wo, g_woa_hi, g_woa_lo, i - WN0, 192, 768, 0, 288);
    } else if (i < WN0 + WN1 + WN2) {
        wput(wa, g_woa_hi, g_woa_lo, i - WN0 - WN1, 96, 768, 192, 288);
    } else if (i < WN0 + WN1 + WN2 + WN3) {
        wput(wu, g_wu_hi, g_wu_lo, i - WN0 - WN1 - WN2, 256, 256, 0, 256);
    } else if (i < WN0 + WN1 + WN2 + WN3 + 288) {
        int j = i - (WN0 + WN1 + WN2 + WN3);
        g_boa[j] = j < 192 ? bo[j] : ba[j - 192];
    }
}

// ---------------- tensor-core implicit-GEMM 3x3 conv body ----------------
// M=128 pixels (2 rows) x NTILE couts. SW128-swizzled smem rows (128B: hi chunks 0-3,
// lo chunks 4-7, chunk ^= row&7). A double-buffered (next chunk staged at tap 7),
// B double-buffered (distance 1). Static wait schedule: wait_group 1 at tap 8, else 0.
template<int CIN, int NTILE, bool TMAJOR>
__device__ __forceinline__ void conv_body(
         int bx, int by, int img,
         const __nv_bfloat16* __restrict__ in_hi, const __nv_bfloat16* __restrict__ in_lo,
         const __nv_bfloat16* __restrict__ wt_hi, const __nv_bfloat16* __restrict__ wt_lo,
         const float* __restrict__ bias, float* __restrict__ out, int cout_total)
{
    extern __shared__ unsigned char smem_raw[];
    const unsigned sm_base = (unsigned)__cvta_generic_to_shared(smem_raw);
    const unsigned sA = sm_base;                       // 2 x A_BUF_B
    const unsigned sB = sm_base + 2 * A_BUF_B;         // 2 x B_SLOT_B

    const int tid = threadIdx.x;
    const int lane = tid & 31, warp = tid >> 5;
    const int gid = lane >> 2, tig = lane & 3;        // epilogue fragment coords
    const int jj = lane >> 3, rr = lane & 7;          // ldmatrix lane coords
    const int warpM = warp & 3, warpN = warp >> 2;

    constexpr int NA = NTILE / 16;                    // n-frags (8 or 6)
    constexpr int NWARP = NTILE / 2;                  // n span per warp (64 or 48)
    constexpr int NCHUNK = CIN / 32;
    const int NTAP_TOT = NCHUNK * 9;

    const int Mbase = bx * 128;
    const int Nbase = by * NTILE;
    const int y0    = bx * 2;

    float acc[2][NA][4];
    #pragma unroll
    for (int ma = 0; ma < 2; ma++)
        #pragma unroll
        for (int na = 0; na < NA; na++)
            #pragma unroll
            for (int q = 0; q < 4; q++) acc[ma][na][q] = 0.f;

    // stage A halo for chunk c into buffer c&1 (always commits a group)
    auto stage_a = [&](int c) {
        if (c < NCHUNK) {
            const unsigned abuf = sA + (unsigned)((c & 1) * A_BUF_B);
            const int cb = c * 32;
            #pragma unroll 1
            for (int i = tid; i < A_POS * 8; i += 256) {
                int pos = i >> 3, sub = i & 7;
                int hf = sub >> 2, seg = sub & 3;
                int ry = pos / 66, col = pos % 66;
                int gy = y0 - 1 + ry, gx = col - 1;
                int ok = ((unsigned)gy < 64u && (unsigned)gx < 64u) ? 16 : 0;
                int gyc = gy < 0 ? 0 : (gy > 63 ? 63 : gy);
                int gxc = gx < 0 ? 0 : (gx > 63 ? 63 : gx);
                const __nv_bfloat16* src = (hf ? in_lo : in_hi)
                    + ((size_t)(img * HW + gyc * 64 + gxc)) * CIN + cb + seg * 8;
                unsigned chunk = (unsigned)((hf * 4 + seg) ^ (pos & 7));
                cp16(abuf + (unsigned)(pos * A_ROW_B) + chunk * 16, src, ok);
            }
        }
        asm volatile("cp.async.commit_group;\n" ::);
    };

    // issue B slab for global tap g into slot g&1 (always commits a group)
    auto issue_b = [&](int g) {
        if (g < NTAP_TOT) {
            int cbb = (g / 9) * 32;
            int tp  = g % 9;
            const unsigned slot = sB + (unsigned)((g & 1) * B_SLOT_B);
            #pragma unroll 1
            for (int i = tid; i < NTILE * 8; i += 256) {
                int n = i >> 3, sub = i & 7;
                int hf = sub >> 2, seg = sub & 3;
                size_t gsrc = ((size_t)(tp * cout_total + Nbase + n)) * CIN + cbb + seg * 8;
                unsigned chunk = (unsigned)((hf * 4 + seg) ^ (n & 7));
                cp16(slot + (unsigned)(n * 128) + chunk * 16, (hf ? wt_lo : wt_hi) + gsrc, 16);
            }
        }
        asm volatile("cp.async.commit_group;\n" ::);
    };

    stage_a(0);
    issue_b(0);

    int g = 0;
    #pragma unroll 1
    for (int c = 0; c < NCHUNK; c++) {
        const unsigned abuf = sA + (unsigned)((c & 1) * A_BUF_B);
        #pragma unroll 1
        for (int tap = 0; tap < 9; tap++, g++) {
            // B(g) committed one tap ago; A(c) committed >=2 taps ago.
            // At tap 8 the youngest group is A(c+1) (committed at tap 7) -> allow it pending.
            if (tap == 8) asm volatile("cp.async.wait_group 1;\n" ::);
            else          asm volatile("cp.async.wait_group 0;\n" ::);
            __syncthreads();

            issue_b(g + 1);
            if (tap == 7) stage_a(c + 1);

            const int dy = tap / 3, dx = tap - dy * 3;
            const unsigned slot = sB + (unsigned)((g & 1) * B_SLOT_B);

            #pragma unroll
            for (int ks = 0; ks < 2; ks++) {
                unsigned ra_h[2][4], ra_l[2][4];
                const unsigned achunk_h = (unsigned)(ks * 2 + (jj >> 1));
                #pragma unroll
                for (int ma = 0; ma < 2; ma++) {
                    int pixel = warpM * 32 + ma * 16 + ((jj & 1) << 3) + rr;
                    int yy = (pixel >> 6) + dy;
                    int xx = (pixel & 63) + dx;
                    int pos = yy * 66 + xx;
                    unsigned rbase = abuf + (unsigned)(pos * A_ROW_B);
                    unsigned sw = (unsigned)(pos & 7);
                    ldsm4(ra_h[ma], rbase + ((achunk_h       ^ sw) << 4));
                    ldsm4(ra_l[ma], rbase + (((achunk_h + 4) ^ sw) << 4));
                }
                const unsigned bchunk_h = (unsigned)(ks * 2 + (jj & 1));
                #pragma unroll
                for (int np = 0; np < NA / 2; np++) {
                    int n = warpN * NWARP + (np * 2 + (jj >> 1)) * 8 + rr;
                    unsigned nbase = slot + (unsigned)(n * 128);
                    unsigned sw = (unsigned)(n & 7);
                    unsigned rbh[4], rbl[4];
                    ldsm4(rbh, nbase + ((bchunk_h       ^ sw) << 4));
                    ldsm4(rbl, nbase + (((bchunk_h + 4) ^ sw) << 4));
                    #pragma unroll
                    for (int ma = 0; ma < 2; ma++) {
                        mma16816(acc[ma][np * 2],     ra_h[ma], rbh[0], rbh[1]);
                        mma16816(acc[ma][np * 2],     ra_h[ma], rbl[0], rbl[1]);
                        mma16816(acc[ma][np * 2],     ra_l[ma], rbh[0], rbh[1]);
                        mma16816(acc[ma][np * 2 + 1], ra_h[ma], rbh[2], rbh[3]);
                        mma16816(acc[ma][np * 2 + 1], ra_h[ma], rbl[2], rbl[3]);
                        mma16816(acc[ma][np * 2 + 1], ra_l[ma], rbh[2], rbh[3]);
                    }
                }
            }
        }
    }

    // ---- epilogue ----
    #pragma unroll
    for (int ma = 0; ma < 2; ma++) {
        int pix = Mbase + warpM * 32 + ma * 16 + gid;
        #pragma unroll
        for (int na = 0; na < NA; na++) {
            int co = Nbase + warpN * NWARP + na * 8 + tig * 2;
            float bv0 = bias[co], bv1 = bias[co + 1];
            if (TMAJOR) {
                float2* p0 = reinterpret_cast<float2*>(out + ((size_t)img * HW + pix) * cout_total + co);
                float2* p1 = reinterpret_cast<float2*>(out + ((size_t)img * HW + pix + 8) * cout_total + co);
                *p0 = make_float2(acc[ma][na][0] + bv0, acc[ma][na][1] + bv1);
                *p1 = make_float2(acc[ma][na][2] + bv0, acc[ma][na][3] + bv1);
            } else {
                out[((size_t)img * cout_total + co)     * HW + pix]     = acc[ma][na][0] + bv0;
                out[((size_t)img * cout_total + co + 1) * HW + pix]     = acc[ma][na][1] + bv1;
                out[((size_t)img * cout_total + co)     * HW + pix + 8] = acc[ma][na][2] + bv0;
                out[((size_t)img * cout_total + co + 1) * HW + pix + 8] = acc[ma][na][3] + bv1;
            }
        }
    }
}

// ---- merged launch: oa conv (384 long CTAs) first, then value conv (768 short) ----
__global__ void __launch_bounds__(256, 2)
conv_pair(const float* __restrict__ b_value)
{
    int bxg = blockIdx.x;
    if (bxg < 384) {
        int x = bxg & 31, y = (bxg >> 5) % 3, img = bxg / 96;
        conv_body<768, 96, true>(x, y, img, g_q_hi, g_q_lo, g_woa_hi, g_woa_lo,
                                 g_boa, g_oa_t, 288);
    } else {
        int t = bxg - 384;
        int x = t & 31, y = (t >> 5) & 1, img = t >> 6;
        conv_body<256, 128, true>(x, y, img, g_flat_hi, g_flat_lo, g_wv_hi, g_wv_lo,
                                  b_value, g_value_t, 256);
    }
}

// ---- out conv (depends on msda) ----
__global__ void __launch_bounds__(256, 2)
conv_out(const float* __restrict__ b_out, float* __restrict__ out)
{
    conv_body<256, 128, false>(blockIdx.x, blockIdx.y, blockIdx.z,
                               g_samp_hi, g_samp_lo, g_wu_hi, g_wu_lo, b_out, out, 256);
}

// ---------------- MSDA sampling + fused softmax; writes bf16 hi/lo -----------------
__global__ __launch_bounds__(256)
void msda_kernel(const float* __restrict__ refp)
{
    int gw = blockIdx.x * 8 + (threadIdx.x >> 5);
    int lane = threadIdx.x & 31;
    int head = gw & 7;
    int pix  = (gw >> 3) & 4095;
    int b    = gw >> 15;

    size_t tok = (size_t)b * HW + pix;
    const float* op = g_oa_t + tok * 288;
    const float* ap = op + 192 + head * 12;

    float lg[12]; float mx = -1e30f;
    #pragma unroll
    for (int j = 0; j < 12; j++) { lg[j] = ap[j]; mx = fmaxf(mx, lg[j]); }
    float den = 0.f;
    #pragma unroll
    for (int j = 0; j < 12; j++) { lg[j] = expf(lg[j] - mx); den += lg[j]; }
    float rden = 1.f / den;

    float acc = 0.f;
    #pragma unroll
    for (int l = 0; l < 3; l++) {
        float rx = refp[(tok * 3 + l) * 2 + 0];
        float ry = refp[(tok * 3 + l) * 2 + 1];
        const float* vb = g_value_t + ((size_t)(b * 3 + l) * HW) * 256 + head * 32 + lane;
        #pragma unroll
        for (int p = 0; p < 4; p++) {
            int ch = ((head * 3 + l) * 4 + p) * 2;
            float ox = op[ch], oy = op[ch + 1];
            float a = lg[l * 4 + p] * rden;
            float xf = rx * 64.f + ox - 0.5f;
            float yf = ry * 64.f + oy - 0.5f;
            float x0f = floorf(xf), y0f = floorf(yf);
            int x0 = (int)x0f, y0 = (int)y0f;
            float lx = xf - x0f, ly = yf - y0f;
            float w00 = (1.f - lx) * (1.f - ly) * a;
            float w10 = lx * (1.f - ly) * a;
            float w01 = (1.f - lx) * ly * a;
            float w11 = lx * ly * a;
            if ((unsigned)x0       < 64u && (unsigned)y0       < 64u) acc += w00 * vb[(size_t)(y0 * 64 + x0) * 256];
            if ((unsigned)(x0 + 1) < 64u && (unsigned)y0       < 64u) acc += w10 * vb[(size_t)(y0 * 64 + x0 + 1) * 256];
            if ((unsigned)x0       < 64u && (unsigned)(y0 + 1) < 64u) acc += w01 * vb[(size_t)((y0 + 1) * 64 + x0) * 256];
            if ((unsigned)(x0 + 1) < 64u && (unsigned)(y0 + 1) < 64u) acc += w11 * vb[(size_t)((y0 + 1) * 64 + x0 + 1) * 256];
        }
    }
    __nv_bfloat16 h = __float2bfloat16(acc);
    size_t o = tok * 256 + head * 32 + lane;
    g_samp_hi[o] = h;
    g_samp_lo[o] = __float2bfloat16(acc - __bfloat162float(h));
}

// ---------------- launcher ----------------------------------------------------------
extern "C" void kernel_launch(void* const* d_in, const int* in_sizes, int n_in,
                              void* d_out, int out_size)
{
    const float* query   = (const float*)d_in[0];
    const float* refp    = (const float*)d_in[1];
    const float* flat    = (const float*)d_in[2];
    const float* w_value = (const float*)d_in[6];
    const float* b_value = (const float*)d_in[7];
    const float* w_off   = (const float*)d_in[8];
    const float* b_off   = (const float*)d_in[9];
    const float* w_attn  = (const float*)d_in[10];
    const float* b_attn  = (const float*)d_in[11];
    const float* w_out   = (const float*)d_in[12];
    const float* b_out   = (const float*)d_in[13];

    __nv_bfloat16 *q_hi, *q_lo, *f_hi, *f_lo;
    cudaGetSymbolAddress((void**)&q_hi, g_q_hi);
    cudaGetSymbolAddress((void**)&q_lo, g_q_lo);
    cudaGetSymbolAddress((void**)&f_hi, g_flat_hi);
    cudaGetSymbolAddress((void**)&f_lo, g_flat_lo);

    cudaFuncSetAttribute(conv_pair, cudaFuncAttributeMaxDynamicSharedMemorySize, SMEM_BYTES);
    cudaFuncSetAttribute(conv_out,  cudaFuncAttributeMaxDynamicSharedMemorySize, SMEM_BYTES);

    // launch 0..2: input conversions + all weight prep (fused)
    chlast_split<<<dim3(128, 8, 12), dim3(32, 8)>>>(flat, f_hi, f_lo, 256);
    chlast_split<<<dim3(128, 24, 4), dim3(32, 8)>>>(query, q_hi, q_lo, 768);
    wprep<<<(WN0 + WN1 + WN2 + WN3 + 288 + 255) / 256, 256>>>(w_value, w_off, w_attn, w_out, b_off, b_attn);

    // launch 3 (ncu window): merged value + off/attn convs, long CTAs first
    conv_pair<<<1152, 256, SMEM_BYTES>>>(b_value);

    // launch 4: deformable attention sampling
    msda_kernel<<<(4 * HW * 8) / 8, 256>>>(refp);

    // launch 5: output conv -> NCHW d_out
    conv_out<<<dim3(32, 2, 4), 256, SMEM_BYTES>>>(b_out, (float*)d_out);
}

// round 9
// speedup vs baseline: 1.0032x; 1.0032x over previous
#include <cuda_runtime.h>
#include <cuda_bf16.h>
#include <cstdint>
#include <math.h>

#define HW 4096
#define A_POS (4 * 66)              // halo positions per chunk tile (4 rows x 66 cols)
#define A_ROW_B 128                 // 32ch hi (64B) + 32ch lo (64B), SW128 swizzled
#define A_BUF_B (A_POS * A_ROW_B)   // 33792 B per A buffer
#define B_SLOT_B (128 * 128)        // 16384 B per B slot (<=128 n rows x 128B)
#define SMEM_BYTES (2 * A_BUF_B + 2 * B_SLOT_B)   // 100352 B -> 2 CTAs/SM

// ---------------- device scratch ----------------
__device__ __nv_bfloat16 g_q_hi   [4u * 4096u * 768u];
__device__ __nv_bfloat16 g_q_lo   [4u * 4096u * 768u];
__device__ __nv_bfloat16 g_flat_hi[12u * 4096u * 256u];
__device__ __nv_bfloat16 g_flat_lo[12u * 4096u * 256u];
__device__ __nv_bfloat16 g_samp_hi[4u * 4096u * 256u];
__device__ __nv_bfloat16 g_samp_lo[4u * 4096u * 256u];
__device__ float g_value_t[12u * 4096u * 256u];
__device__ float g_oa_t   [4u * 4096u * 288u];        // merged off(0:192)+attn(192:288), token-major
__device__ float g_boa    [288];
__device__ __nv_bfloat16 g_wv_hi [9u * 256u * 256u], g_wv_lo [9u * 256u * 256u];
__device__ __nv_bfloat16 g_woa_hi[9u * 288u * 768u], g_woa_lo[9u * 288u * 768u];
__device__ __nv_bfloat16 g_wu_hi [9u * 256u * 256u], g_wu_lo [9u * 256u * 256u];

// ---------------- helpers ----------------
__device__ __forceinline__ void mma16816(float* c, const unsigned* a, unsigned b0, unsigned b1)
{
    asm volatile("mma.sync.aligned.m16n8k16.row.col.f32.bf16.bf16.f32 "
        "{%0,%1,%2,%3}, {%4,%5,%6,%7}, {%8,%9}, {%0,%1,%2,%3};"
        : "+f"(c[0]), "+f"(c[1]), "+f"(c[2]), "+f"(c[3])
        : "r"(a[0]), "r"(a[1]), "r"(a[2]), "r"(a[3]), "r"(b0), "r"(b1));
}

__device__ __forceinline__ void cp16(unsigned daddr, const void* src, int srcsz)
{
    asm volatile("cp.async.cg.shared.global [%0], [%1], 16, %2;\n"
                 :: "r"(daddr), "l"(src), "r"(srcsz));
}

__device__ __forceinline__ void ldsm4(unsigned* d, unsigned saddr)
{
    asm volatile("ldmatrix.sync.aligned.m8n8.x4.shared.b16 {%0,%1,%2,%3}, [%4];"
        : "=r"(d[0]), "=r"(d[1]), "=r"(d[2]), "=r"(d[3]) : "r"(saddr));
}

// ---------------- conversion kernels ----------------
__global__ void chlast_split(const float* __restrict__ in, __nv_bfloat16* __restrict__ hi,
                             __nv_bfloat16* __restrict__ lo, int C)
{
    __shared__ float t[32][33];
    int img = blockIdx.z;
    int p0 = blockIdx.x * 32, c0 = blockIdx.y * 32;
    int tx = threadIdx.x;
    for (int j = threadIdx.y; j < 32; j += 8)
        t[j][tx] = in[((size_t)img * C + c0 + j) * HW + p0 + tx];
    __syncthreads();
    for (int j = threadIdx.y; j < 32; j += 8) {
        float v = t[tx][j];
        __nv_bfloat16 h = __float2bfloat16(v);
        size_t o = ((size_t)img * HW + p0 + j) * C + c0 + tx;
        hi[o] = h;
        lo[o] = __float2bfloat16(v - __bfloat162float(h));
    }
}

// put one weight element: w[co][ci][3][3] -> buf[tap][co_off+co][ci]
__device__ __forceinline__ void wput(const float* __restrict__ w, __nv_bfloat16* hi,
                                     __nv_bfloat16* lo, int i, int cout, int cin,
                                     int co_off, int cout_buf)
{
    int ci = i % cin; int r = i / cin; int co = r % cout; int tap = r / cout;
    float v = w[((size_t)co * cin + ci) * 9 + tap];
    __nv_bfloat16 h = __float2bfloat16(v);
    size_t o = ((size_t)tap * cout_buf + co_off + co) * cin + ci;
    hi[o] = h;
    lo[o] = __float2bfloat16(v - __bfloat162float(h));
}

#define WN0 (9 * 256 * 256)
#define WN1 (9 * 192 * 768)
#define WN2 (9 * 96  * 768)
#define WN3 (9 * 256 * 256)
__global__ void wprep(const float* __restrict__ wv, const float* __restrict__ wo,
                      const float* __restrict__ wa, const float* __restrict__ wu,
                      const float* __restrict__ bo, const float* __restrict__ ba)
{
    int i = blockIdx.x * 256 + threadIdx.x;
    if (i < WN0) {
        wput(wv, g_wv_hi, g_wv_lo, i, 256, 256, 0, 256);
    } else if (i < WN0 + WN1) {
        wput(wo, g_woa_hi, g_woa_lo, i - WN0, 192, 768, 0, 288);
    } else if (i < WN0 + WN1 + WN2) {
        wput(wa, g_woa_hi, g_woa_lo, i - WN0 - WN1, 96, 768, 192, 288);
    } else if (i < WN0 + WN1 + WN2 + WN3) {
        wput(wu, g_wu_hi, g_wu_lo, i - WN0 - WN1 - WN2, 256, 256, 0, 256);
    } else if (i < WN0 + WN1 + WN2 + WN3 + 288) {
        int j = i - (WN0 + WN1 + WN2 + WN3);
        g_boa[j] = j < 192 ? bo[j] : ba[j - 192];
    }
}

// ---------------- tensor-core implicit-GEMM 3x3 conv body ----------------
// M=128 pixels (2 rows) x NTILE couts. SW128-swizzled smem rows (128B: hi chunks 0-3,
// lo chunks 4-7, chunk ^= row&7). A double-buffered (next chunk staged at tap 7),
// B double-buffered (distance 1). Static wait schedule: wait_group 1 at tap 8, else 0.
template<int CIN, int NTILE, bool TMAJOR>
__device__ __forceinline__ void conv_body(
         int bx, int by, int img,
         const __nv_bfloat16* __restrict__ in_hi, const __nv_bfloat16* __restrict__ in_lo,
         const __nv_bfloat16* __restrict__ wt_hi, const __nv_bfloat16* __restrict__ wt_lo,
         const float* __restrict__ bias, float* __restrict__ out, int cout_total)
{
    extern __shared__ unsigned char smem_raw[];
    const unsigned sm_base = (unsigned)__cvta_generic_to_shared(smem_raw);
    const unsigned sA = sm_base;                       // 2 x A_BUF_B
    const unsigned sB = sm_base + 2 * A_BUF_B;         // 2 x B_SLOT_B

    const int tid = threadIdx.x;
    const int lane = tid & 31, warp = tid >> 5;
    const int gid = lane >> 2, tig = lane & 3;        // epilogue fragment coords
    const int jj = lane >> 3, rr = lane & 7;          // ldmatrix lane coords
    const int warpM = warp & 3, warpN = warp >> 2;

    constexpr int NA = NTILE / 16;                    // n-frags (8 or 6)
    constexpr int NWARP = NTILE / 2;                  // n span per warp (64 or 48)
    constexpr int NCHUNK = CIN / 32;
    const int NTAP_TOT = NCHUNK * 9;

    const int Mbase = bx * 128;
    const int Nbase = by * NTILE;
    const int y0    = bx * 2;

    float acc[2][NA][4];
    #pragma unroll
    for (int ma = 0; ma < 2; ma++)
        #pragma unroll
        for (int na = 0; na < NA; na++)
            #pragma unroll
            for (int q = 0; q < 4; q++) acc[ma][na][q] = 0.f;

    // stage A halo for chunk c into buffer c&1 (always commits a group)
    auto stage_a = [&](int c) {
        if (c < NCHUNK) {
            const unsigned abuf = sA + (unsigned)((c & 1) * A_BUF_B);
            const int cb = c * 32;
            #pragma unroll 1
            for (int i = tid; i < A_POS * 8; i += 256) {
                int pos = i >> 3, sub = i & 7;
                int hf = sub >> 2, seg = sub & 3;
                int ry = pos / 66, col = pos % 66;
                int gy = y0 - 1 + ry, gx = col - 1;
                int ok = ((unsigned)gy < 64u && (unsigned)gx < 64u) ? 16 : 0;
                int gyc = gy < 0 ? 0 : (gy > 63 ? 63 : gy);
                int gxc = gx < 0 ? 0 : (gx > 63 ? 63 : gx);
                const __nv_bfloat16* src = (hf ? in_lo : in_hi)
                    + ((size_t)(img * HW + gyc * 64 + gxc)) * CIN + cb + seg * 8;
                unsigned chunk = (unsigned)((hf * 4 + seg) ^ (pos & 7));
                cp16(abuf + (unsigned)(pos * A_ROW_B) + chunk * 16, src, ok);
            }
        }
        asm volatile("cp.async.commit_group;\n" ::);
    };

    // issue B slab for global tap g into slot g&1 (always commits a group)
    auto issue_b = [&](int g) {
        if (g < NTAP_TOT) {
            int cbb = (g / 9) * 32;
            int tp  = g % 9;
            const unsigned slot = sB + (unsigned)((g & 1) * B_SLOT_B);
            #pragma unroll 1
            for (int i = tid; i < NTILE * 8; i += 256) {
                int n = i >> 3, sub = i & 7;
                int hf = sub >> 2, seg = sub & 3;
                size_t gsrc = ((size_t)(tp * cout_total + Nbase + n)) * CIN + cbb + seg * 8;
                unsigned chunk = (unsigned)((hf * 4 + seg) ^ (n & 7));
                cp16(slot + (unsigned)(n * 128) + chunk * 16, (hf ? wt_lo : wt_hi) + gsrc, 16);
            }
        }
        asm volatile("cp.async.commit_group;\n" ::);
    };

    stage_a(0);
    issue_b(0);

    int g = 0;
    #pragma unroll 1
    for (int c = 0; c < NCHUNK; c++) {
        const unsigned abuf = sA + (unsigned)((c & 1) * A_BUF_B);
        #pragma unroll 1
        for (int tap = 0; tap < 9; tap++, g++) {
            // B(g) committed one tap ago; A(c) committed >=2 taps ago.
            // At tap 8 the youngest group is A(c+1) (committed at tap 7) -> allow it pending.
            if (tap == 8) asm volatile("cp.async.wait_group 1;\n" ::);
            else          asm volatile("cp.async.wait_group 0;\n" ::);
            __syncthreads();

            issue_b(g + 1);
            if (tap == 7) stage_a(c + 1);

            const int dy = tap / 3, dx = tap - dy * 3;
            const unsigned slot = sB + (unsigned)((g & 1) * B_SLOT_B);

            #pragma unroll
            for (int ks = 0; ks < 2; ks++) {
                unsigned ra_h[2][4], ra_l[2][4];
                const unsigned achunk_h = (unsigned)(ks * 2 + (jj >> 1));
                #pragma unroll
                for (int ma = 0; ma < 2; ma++) {
                    int pixel = warpM * 32 + ma * 16 + ((jj & 1) << 3) + rr;
                    int yy = (pixel >> 6) + dy;
                    int xx = (pixel & 63) + dx;
                    int pos = yy * 66 + xx;
                    unsigned rbase = abuf + (unsigned)(pos * A_ROW_B);
                    unsigned sw = (unsigned)(pos & 7);
                    ldsm4(ra_h[ma], rbase + ((achunk_h       ^ sw) << 4));
                    ldsm4(ra_l[ma], rbase + (((achunk_h + 4) ^ sw) << 4));
                }
                const unsigned bchunk_h = (unsigned)(ks * 2 + (jj & 1));
                #pragma unroll
                for (int np = 0; np < NA / 2; np++) {
                    int n = warpN * NWARP + (np * 2 + (jj >> 1)) * 8 + rr;
                    unsigned nbase = slot + (unsigned)(n * 128);
                    unsigned sw = (unsigned)(n & 7);
                    unsigned rbh[4], rbl[4];
                    ldsm4(rbh, nbase + ((bchunk_h       ^ sw) << 4));
                    ldsm4(rbl, nbase + (((bchunk_h + 4) ^ sw) << 4));
                    #pragma unroll
                    for (int ma = 0; ma < 2; ma++) {
                        mma16816(acc[ma][np * 2],     ra_h[ma], rbh[0], rbh[1]);
                        mma16816(acc[ma][np * 2],     ra_h[ma], rbl[0], rbl[1]);
                        mma16816(acc[ma][np * 2],     ra_l[ma], rbh[0], rbh[1]);
                        mma16816(acc[ma][np * 2 + 1], ra_h[ma], rbh[2], rbh[3]);
                        mma16816(acc[ma][np * 2 + 1], ra_h[ma], rbl[2], rbl[3]);
                        mma16816(acc[ma][np * 2 + 1], ra_l[ma], rbh[2], rbh[3]);
                    }
                }
            }
        }
    }

    // ---- epilogue ----
    #pragma unroll
    for (int ma = 0; ma < 2; ma++) {
        int pix = Mbase + warpM * 32 + ma * 16 + gid;
        #pragma unroll
        for (int na = 0; na < NA; na++) {
            int co = Nbase + warpN * NWARP + na * 8 + tig * 2;
            float bv0 = bias[co], bv1 = bias[co + 1];
            if (TMAJOR) {
                float2* p0 = reinterpret_cast<float2*>(out + ((size_t)img * HW + pix) * cout_total + co);
                float2* p1 = reinterpret_cast<float2*>(out + ((size_t)img * HW + pix + 8) * cout_total + co);
                *p0 = make_float2(acc[ma][na][0] + bv0, acc[ma][na][1] + bv1);
                *p1 = make_float2(acc[ma][na][2] + bv0, acc[ma][na][3] + bv1);
            } else {
                out[((size_t)img * cout_total + co)     * HW + pix]     = acc[ma][na][0] + bv0;
                out[((size_t)img * cout_total + co + 1) * HW + pix]     = acc[ma][na][1] + bv1;
                out[((size_t)img * cout_total + co)     * HW + pix + 8] = acc[ma][na][2] + bv0;
                out[((size_t)img * cout_total + co + 1) * HW + pix + 8] = acc[ma][na][3] + bv1;
            }
        }
    }
}

// ---- merged launch: oa conv (384 long CTAs) first, then value conv (768 short) ----
__global__ void __launch_bounds__(256, 2)
conv_pair(const float* __restrict__ b_value)
{
    int bxg = blockIdx.x;
    if (bxg < 384) {
        int x = bxg & 31, y = (bxg >> 5) % 3, img = bxg / 96;
        conv_body<768, 96, true>(x, y, img, g_q_hi, g_q_lo, g_woa_hi, g_woa_lo,
                                 g_boa, g_oa_t, 288);
    } else {
        int t = bxg - 384;
        int x = t & 31, y = (t >> 5) & 1, img = t >> 6;
        conv_body<256, 128, true>(x, y, img, g_flat_hi, g_flat_lo, g_wv_hi, g_wv_lo,
                                  b_value, g_value_t, 256);
    }
}

// ---- out conv (depends on msda) ----
__global__ void __launch_bounds__(256, 2)
conv_out(const float* __restrict__ b_out, float* __restrict__ out)
{
    conv_body<256, 128, false>(blockIdx.x, blockIdx.y, blockIdx.z,
                               g_samp_hi, g_samp_lo, g_wu_hi, g_wu_lo, b_out, out, 256);
}

// ---------------- MSDA sampling + fused softmax; writes bf16 hi/lo -----------------
__global__ __launch_bounds__(256)
void msda_kernel(const float* __restrict__ refp)
{
    int gw = blockIdx.x * 8 + (threadIdx.x >> 5);
    int lane = threadIdx.x & 31;
    int head = gw & 7;
    int pix  = (gw >> 3) & 4095;
    int b    = gw >> 15;

    size_t tok = (size_t)b * HW + pix;
    const float* op = g_oa_t + tok * 288;
    const float* ap = op + 192 + head * 12;

    float lg[12]; float mx = -1e30f;
    #pragma unroll
    for (int j = 0; j < 12; j++) { lg[j] = ap[j]; mx = fmaxf(mx, lg[j]); }
    float den = 0.f;
    #pragma unroll
    for (int j = 0; j < 12; j++) { lg[j] = expf(lg[j] - mx); den += lg[j]; }
    float rden = 1.f / den;

    float acc = 0.f;
    #pragma unroll
    for (int l = 0; l < 3; l++) {
        float rx = refp[(tok * 3 + l) * 2 + 0];
        float ry = refp[(tok * 3 + l) * 2 + 1];
        const float* vb = g_value_t + ((size_t)(b * 3 + l) * HW) * 256 + head * 32 + lane;
        #pragma unroll
        for (int p = 0; p < 4; p++) {
            int ch = ((head * 3 + l) * 4 + p) * 2;
            float ox = op[ch], oy = op[ch + 1];
            float a = lg[l * 4 + p] * rden;
            float xf = rx * 64.f + ox - 0.5f;
            float yf = ry * 64.f + oy - 0.5f;
            float x0f = floorf(xf), y0f = floorf(yf);
            int x0 = (int)x0f, y0 = (int)y0f;
            float lx = xf - x0f, ly = yf - y0f;
            float w00 = (1.f - lx) * (1.f - ly) * a;
            float w10 = lx * (1.f - ly) * a;
            float w01 = (1.f - lx) * ly * a;
            float w11 = lx * ly * a;
            if ((unsigned)x0       < 64u && (unsigned)y0       < 64u) acc += w00 * vb[(size_t)(y0 * 64 + x0) * 256];
            if ((unsigned)(x0 + 1) < 64u && (unsigned)y0       < 64u) acc += w10 * vb[(size_t)(y0 * 64 + x0 + 1) * 256];
            if ((unsigned)x0       < 64u && (unsigned)(y0 + 1) < 64u) acc += w01 * vb[(size_t)((y0 + 1) * 64 + x0) * 256];
            if ((unsigned)(x0 + 1) < 64u && (unsigned)(y0 + 1) < 64u) acc += w11 * vb[(size_t)((y0 + 1) * 64 + x0 + 1) * 256];
        }
    }
    __nv_bfloat16 h = __float2bfloat16(acc);
    size_t o = tok * 256 + head * 32 + lane;
    g_samp_hi[o] = h;
    g_samp_lo[o] = __float2bfloat16(acc - __bfloat162float(h));
}

// ---------------- launcher ----------------------------------------------------------
extern "C" void kernel_launch(void* const* d_in, const int* in_sizes, int n_in,
                              void* d_out, int out_size)
{
    const float* query   = (const float*)d_in[0];
    const float* refp    = (const float*)d_in[1];
    const float* flat    = (const float*)d_in[2];
    const float* w_value = (const float*)d_in[6];
    const float* b_value = (const float*)d_in[7];
    const float* w_off   = (const float*)d_in[8];
    const float* b_off   = (const float*)d_in[9];
    const float* w_attn  = (const float*)d_in[10];
    const float* b_attn  = (const float*)d_in[11];
    const float* w_out   = (const float*)d_in[12];
    const float* b_out   = (const float*)d_in[13];

    __nv_bfloat16 *q_hi, *q_lo, *f_hi, *f_lo;
    cudaGetSymbolAddress((void**)&q_hi, g_q_hi);
    cudaGetSymbolAddress((void**)&q_lo, g_q_lo);
    cudaGetSymbolAddress((void**)&f_hi, g_flat_hi);
    cudaGetSymbolAddress((void**)&f_lo, g_flat_lo);

    cudaFuncSetAttribute(conv_pair, cudaFuncAttributeMaxDynamicSharedMemorySize, SMEM_BYTES);
    cudaFuncSetAttribute(conv_out,  cudaFuncAttributeMaxDynamicSharedMemorySize, SMEM_BYTES);

    // launch 0..2: input conversions + all weight prep (fused)
    chlast_split<<<dim3(128, 8, 12), dim3(32, 8)>>>(flat, f_hi, f_lo, 256);
    chlast_split<<<dim3(128, 24, 4), dim3(32, 8)>>>(query, q_hi, q_lo, 768);
    wprep<<<(WN0 + WN1 + WN2 + WN3 + 288 + 255) / 256, 256>>>(w_value, w_off, w_attn, w_out, b_off, b_attn);

    // launch 3 (ncu window): merged value + off/attn convs, long CTAs first
    conv_pair<<<1152, 256, SMEM_BYTES>>>(b_value);

    // launch 4: deformable attention sampling
    msda_kernel<<<(4 * HW * 8) / 8, 256>>>(refp);

    // launch 5: output conv -> NCHW d_out
    conv_out<<<dim3(32, 2, 4), 256, SMEM_BYTES>>>(b_out, (float*)d_out);
}

// round 11
// speedup vs baseline: 1.0420x; 1.0387x over previous
#include <cuda_runtime.h>
#include <cuda_bf16.h>
#include <cstdint>
#include <math.h>

#define HW 4096
#define CPA_B 80                    // A smem row stride (bytes), 16B-aligned for ldmatrix
#define CPB_B 80                    // B smem row stride (bytes)
#define A_POS (4 * 66)              // halo positions per chunk tile
#define A_HALF_B (A_POS * CPA_B)    // bytes per hi/lo half
#define B_SLOT_B (2 * 128 * CPB_B)  // slot sized for 128 rows (96 uses a subset)
#define SMEM_BYTES (2 * A_HALF_B + 3 * B_SLOT_B)   // 103680

// ---------------- device scratch ----------------
__device__ __nv_bfloat16 g_q_hi   [4u * 4096u * 768u];
__device__ __nv_bfloat16 g_q_lo   [4u * 4096u * 768u];
__device__ __nv_bfloat16 g_flat_hi[12u * 4096u * 256u];
__device__ __nv_bfloat16 g_flat_lo[12u * 4096u * 256u];
__device__ __nv_bfloat16 g_samp_hi[4u * 4096u * 256u];
__device__ __nv_bfloat16 g_samp_lo[4u * 4096u * 256u];
__device__ float g_value_t[12u * 4096u * 256u];
__device__ float g_oa_t   [4u * 4096u * 288u];        // merged off(0:192)+attn(192:288), token-major
__device__ float g_boa    [288];
__device__ __nv_bfloat16 g_wv_hi [9u * 256u * 256u], g_wv_lo [9u * 256u * 256u];
__device__ __nv_bfloat16 g_woa_hi[9u * 288u * 768u], g_woa_lo[9u * 288u * 768u];
__device__ __nv_bfloat16 g_wu_hi [9u * 256u * 256u], g_wu_lo [9u * 256u * 256u];

// ---------------- helpers ----------------
__device__ __forceinline__ void mma16816(float* c, const unsigned* a, unsigned b0, unsigned b1)
{
    asm volatile("mma.sync.aligned.m16n8k16.row.col.f32.bf16.bf16.f32 "
        "{%0,%1,%2,%3}, {%4,%5,%6,%7}, {%8,%9}, {%0,%1,%2,%3};"
        : "+f"(c[0]), "+f"(c[1]), "+f"(c[2]), "+f"(c[3])
        : "r"(a[0]), "r"(a[1]), "r"(a[2]), "r"(a[3]), "r"(b0), "r"(b1));
}

__device__ __forceinline__ void cp16(unsigned daddr, const void* src, int srcsz)
{
    asm volatile("cp.async.cg.shared.global [%0], [%1], 16, %2;\n"
                 :: "r"(daddr), "l"(src), "r"(srcsz));
}

__device__ __forceinline__ void ldsm4(unsigned* d, unsigned saddr)
{
    asm volatile("ldmatrix.sync.aligned.m8n8.x4.shared.b16 {%0,%1,%2,%3}, [%4];"
        : "=r"(d[0]), "=r"(d[1]), "=r"(d[2]), "=r"(d[3]) : "r"(saddr));
}

// ---------------- conversion kernels ----------------
__global__ void chlast_split(const float* __restrict__ in, __nv_bfloat16* __restrict__ hi,
                             __nv_bfloat16* __restrict__ lo, int C)
{
    __shared__ float t[32][33];
    int img = blockIdx.z;
    int p0 = blockIdx.x * 32, c0 = blockIdx.y * 32;
    int tx = threadIdx.x;
    for (int j = threadIdx.y; j < 32; j += 8)
        t[j][tx] = in[((size_t)img * C + c0 + j) * HW + p0 + tx];
    __syncthreads();
    for (int j = threadIdx.y; j < 32; j += 8) {
        float v = t[tx][j];
        __nv_bfloat16 h = __float2bfloat16(v);
        size_t o = ((size_t)img * HW + p0 + j) * C + c0 + tx;
        hi[o] = h;
        lo[o] = __float2bfloat16(v - __bfloat162float(h));
    }
}

__device__ __forceinline__ void wput(const float* __restrict__ w, __nv_bfloat16* hi,
                                     __nv_bfloat16* lo, int i, int cout, int cin,
                                     int co_off, int cout_buf)
{
    int ci = i % cin; int r = i / cin; int co = r % cout; int tap = r / cout;
    float v = w[((size_t)co * cin + ci) * 9 + tap];
    __nv_bfloat16 h = __float2bfloat16(v);
    size_t o = ((size_t)tap * cout_buf + co_off + co) * cin + ci;
    hi[o] = h;
    lo[o] = __float2bfloat16(v - __bfloat162float(h));
}

#define WN0 (9 * 256 * 256)
#define WN1 (9 * 192 * 768)
#define WN2 (9 * 96  * 768)
#define WN3 (9 * 256 * 256)
__global__ void wprep(const float* __restrict__ wv, const float* __restrict__ wo,
                      const float* __restrict__ wa, const float* __restrict__ wu,
                      const float* __restrict__ bo, const float* __restrict__ ba)
{
    int i = blockIdx.x * 256 + threadIdx.x;
    if (i < WN0) wput(wv, g_wv_hi, g_wv_lo, i, 256, 256, 0, 256);
    else if (i < WN0 + WN1) wput(wo, g_woa_hi, g_woa_lo, i - WN0, 192, 768, 0, 288);
    else if (i < WN0 + WN1 + WN2) wput(wa, g_woa_hi, g_woa_lo, i - WN0 - WN1, 96, 768, 192, 288);
    else if (i < WN0 + WN1 + WN2 + WN3) wput(wu, g_wu_hi, g_wu_lo, i - WN0 - WN1 - WN2, 256, 256, 0, 256);
    else if (i < WN0 + WN1 + WN2 + WN3 + 288) {
        int j = i - (WN0 + WN1 + WN2 + WN3);
        g_boa[j] = j < 192 ? bo[j] : ba[j - 192];
    }
}

// ---------------- tensor-core implicit-GEMM 3x3 conv body (round-7 proven) ----------
template<int CIN, int NTILE, bool TMAJOR>
__device__ __forceinline__ void conv_body(
         int bx, int by, int img,
         const __nv_bfloat16* __restrict__ in_hi, const __nv_bfloat16* __restrict__ in_lo,
         const __nv_bfloat16* __restrict__ wt_hi, const __nv_bfloat16* __restrict__ wt_lo,
         const float* __restrict__ bias, float* __restrict__ out, int cout_total)
{
    extern __shared__ unsigned char smem_raw[];
    const unsigned sm_base = (unsigned)__cvta_generic_to_shared(smem_raw);
    const unsigned sA  = sm_base;                     // A hi then lo
    const unsigned sBb = sm_base + 2 * A_HALF_B;      // 3 slots x (hi,lo)

    const int tid = threadIdx.x;
    const int lane = tid & 31, warp = tid >> 5;
    const int gid = lane >> 2, tig = lane & 3;
    const int jj = lane >> 3, rr = lane & 7;
    const int warpM = warp & 3, warpN = warp >> 2;

    constexpr int NA = NTILE / 16;
    constexpr int NWARP = NTILE / 2;

    const int Mbase = bx * 128;
    const int Nbase = by * NTILE;
    const int y0    = bx * 2;

    const int NTAP_TOT = (CIN / 32) * 9;

    float acc[2][NA][4];
    #pragma unroll
    for (int ma = 0; ma < 2; ma++)
        #pragma unroll
        for (int na = 0; na < NA; na++)
            #pragma unroll
            for (int q = 0; q < 4; q++) acc[ma][na][q] = 0.f;

    auto issue_b = [&](int g) {
        if (g < NTAP_TOT) {
            int cbb = (g / 9) * 32;
            int tp  = g % 9;
            int slot = g % 3;
            #pragma unroll 1
            for (int i = tid; i < NTILE * 4; i += 256) {
                int n = i >> 2, seg = i & 3;
                size_t gsrc = ((size_t)(tp * cout_total + Nbase + n)) * CIN + cbb + seg * 8;
                cp16(sBb + (unsigned)(((slot * 2 + 0) * 128 + n) * CPB_B + seg * 16), wt_hi + gsrc, 16);
                cp16(sBb + (unsigned)(((slot * 2 + 1) * 128 + n) * CPB_B + seg * 16), wt_lo + gsrc, 16);
            }
        }
        asm volatile("cp.async.commit_group;\n" ::);
    };

    issue_b(0);
    issue_b(1);

    int g = 0;
    #pragma unroll 1
    for (int cb = 0; cb < CIN; cb += 32) {
        __syncthreads();

        #pragma unroll 1
        for (int i = tid; i < A_POS * 8; i += 256) {
            int pos = i >> 3, sub = i & 7;
            int hf = sub >> 2, seg = sub & 3;
            int ry = pos / 66, col = pos % 66;
            int gy = y0 - 1 + ry, gx = col - 1;
            int ok = ((unsigned)gy < 64u && (unsigned)gx < 64u) ? 16 : 0;
            int gyc = gy < 0 ? 0 : (gy > 63 ? 63 : gy);
            int gxc = gx < 0 ? 0 : (gx > 63 ? 63 : gx);
            const __nv_bfloat16* src = (hf ? in_lo : in_hi)
                + ((size_t)(img * HW + gyc * 64 + gxc)) * CIN + cb + seg * 8;
            cp16(sA + (unsigned)(hf * A_HALF_B + pos * CPA_B + seg * 16), src, ok);
        }
        asm volatile("cp.async.commit_group;\n" ::);

        #pragma unroll 1
        for (int tap = 0; tap < 9; tap++, g++) {
            if (tap == 0) asm volatile("cp.async.wait_group 0;\n" ::);
            else          asm volatile("cp.async.wait_group 1;\n" ::);
            __syncthreads();

            const int dy = tap / 3, dx = tap - dy * 3;
            const int slot = g % 3;
            const unsigned sBh = sBb + (unsigned)((slot * 2 + 0) * 128 * CPB_B);
            const unsigned sBl = sBb + (unsigned)((slot * 2 + 1) * 128 * CPB_B);

            #pragma unroll
            for (int ks = 0; ks < 2; ks++) {
                const int kb2 = ks * 32;
                unsigned ra_h[2][4], ra_l[2][4];
                #pragma unroll
                for (int ma = 0; ma < 2; ma++) {
                    int pixel = warpM * 32 + ma * 16 + ((jj & 1) << 3) + rr;
                    int yy = (pixel >> 6) + dy;
                    int xx = (pixel & 63) + dx;
                    unsigned aofs = (unsigned)((yy * 66 + xx) * CPA_B + kb2 + ((jj >> 1) << 4));
                    ldsm4(ra_h[ma], sA + aofs);
                    ldsm4(ra_l[ma], sA + A_HALF_B + aofs);
                }
                #pragma unroll
                for (int np = 0; np < NA / 2; np++) {
                    int n = warpN * NWARP + (np * 2 + (jj >> 1)) * 8 + rr;
                    unsigned bofs = (unsigned)(n * CPB_B + kb2 + ((jj & 1) << 4));
                    unsigned rbh[4], rbl[4];
                    ldsm4(rbh, sBh + bofs);
                    ldsm4(rbl, sBl + bofs);
                    #pragma unroll
                    for (int ma = 0; ma < 2; ma++) {
                        mma16816(acc[ma][np * 2],     ra_h[ma], rbh[0], rbh[1]);
                        mma16816(acc[ma][np * 2],     ra_h[ma], rbl[0], rbl[1]);
                        mma16816(acc[ma][np * 2],     ra_l[ma], rbh[0], rbh[1]);
                        mma16816(acc[ma][np * 2 + 1], ra_h[ma], rbh[2], rbh[3]);
                        mma16816(acc[ma][np * 2 + 1], ra_h[ma], rbl[2], rbl[3]);
                        mma16816(acc[ma][np * 2 + 1], ra_l[ma], rbh[2], rbh[3]);
                    }
                }
            }
            issue_b(g + 2);
        }
    }

    #pragma unroll
    for (int ma = 0; ma < 2; ma++) {
        int pix = Mbase + warpM * 32 + ma * 16 + gid;
        #pragma unroll
        for (int na = 0; na < NA; na++) {
            int co = Nbase + warpN * NWARP + na * 8 + tig * 2;
            float bv0 = bias[co], bv1 = bias[co + 1];
            if (TMAJOR) {
                float2* p0 = reinterpret_cast<float2*>(out + ((size_t)img * HW + pix) * cout_total + co);
                float2* p1 = reinterpret_cast<float2*>(out + ((size_t)img * HW + pix + 8) * cout_total + co);
                *p0 = make_float2(acc[ma][na][0] + bv0, acc[ma][na][1] + bv1);
                *p1 = make_float2(acc[ma][na][2] + bv0, acc[ma][na][3] + bv1);
            } else {
                out[((size_t)img * cout_total + co)     * HW + pix]     = acc[ma][na][0] + bv0;
                out[((size_t)img * cout_total + co + 1) * HW + pix]     = acc[ma][na][1] + bv1;
                out[((size_t)img * cout_total + co)     * HW + pix + 8] = acc[ma][na][2] + bv0;
                out[((size_t)img * cout_total + co + 1) * HW + pix + 8] = acc[ma][na][3] + bv1;
            }
        }
    }
}

__global__ void __launch_bounds__(256, 2)
conv_pair(const float* __restrict__ b_value)
{
    int bxg = blockIdx.x;
    if (bxg < 384) {
        int x = bxg & 31, y = (bxg >> 5) % 3, img = bxg / 96;
        conv_body<768, 96, true>(x, y, img, g_q_hi, g_q_lo, g_woa_hi, g_woa_lo,
                                 g_boa, g_oa_t, 288);
    } else {
        int t = bxg - 384;
        int x = t & 31, y = (t >> 5) & 1, img = t >> 6;
        conv_body<256, 128, true>(x, y, img, g_flat_hi, g_flat_lo, g_wv_hi, g_wv_lo,
                                  b_value, g_value_t, 256);
    }
}

__global__ void __launch_bounds__(256, 2)
conv_out(const float* __restrict__ b_out, float* __restrict__ out)
{
    conv_body<256, 128, false>(blockIdx.x, blockIdx.y, blockIdx.z,
                               g_samp_hi, g_samp_lo, g_wu_hi, g_wu_lo, b_out, out, 256);
}

// ---------------- MSDA v2: lane-parallel softmax + bilinear setup ------------------
// Warp = (b, pix, head); lane j<12 owns point j (level j>>2, point j&3):
// computes logit+exp, bilinear weights & clamped corner indices. Shuffles broadcast.
// Lanes then gather 32 channels per corner (one 128B line) with zero-weight skip.
__global__ __launch_bounds__(256)
void msda_kernel(const float* __restrict__ refp)
{
    const unsigned FULL = 0xFFFFFFFFu;
    int gw = blockIdx.x * 8 + (threadIdx.x >> 5);
    int lane = threadIdx.x & 31;
    int head = gw & 7;
    int pix  = (gw >> 3) & 4095;
    int b    = gw >> 15;

    size_t tok = (size_t)b * HW + pix;
    const float* op = g_oa_t + tok * 288;

    // softmax over 12 logits, lane-parallel
    float lg = (lane < 12) ? op[192 + head * 12 + lane] : -1e30f;
    float mx = lg;
    #pragma unroll
    for (int s = 16; s > 0; s >>= 1) mx = fmaxf(mx, __shfl_xor_sync(FULL, mx, s));
    float e = (lane < 12) ? __expf(lg - mx) : 0.f;
    float den = e;
    #pragma unroll
    for (int s = 16; s > 0; s >>= 1) den += __shfl_xor_sync(FULL, den, s);
    float aw = e / den;                    // lane j: softmax weight of point j

    // offsets: lane j<24 holds op[head*24 + j]; ref: lane j<6 holds refp[tok*6+j]
    float offv = (lane < 24) ? op[head * 24 + lane] : 0.f;
    float refv = (lane < 6) ? refp[tok * 6 + lane] : 0.f;

    // per-point setup in lane j<12
    int lsel = (lane >> 2) * 2;            // level*2 for ref shuffle
    float rx = __shfl_sync(FULL, refv, lsel);
    float ry = __shfl_sync(FULL, refv, lsel + 1);
    float ox = __shfl_sync(FULL, offv, lane * 2 < 32 ? lane * 2 : 0);
    float oy = __shfl_sync(FULL, offv, lane * 2 + 1 < 32 ? lane * 2 + 1 : 0);
    // (lane>=12 shuffles get garbage; never consumed)
    float xf = rx * 64.f + ox - 0.5f;
    float yf = ry * 64.f + oy - 0.5f;
    float x0f = floorf(xf), y0f = floorf(yf);
    int x0 = (int)x0f, y0 = (int)y0f;
    float lx = xf - x0f, ly = yf - y0f;
    float w00 = (1.f - lx) * (1.f - ly) * aw;
    float w10 = lx * (1.f - ly) * aw;
    float w01 = (1.f - lx) * ly * aw;
    float w11 = lx * ly * aw;
    bool vx0 = (unsigned)x0 < 64u, vx1 = (unsigned)(x0 + 1) < 64u;
    bool vy0 = (unsigned)y0 < 64u, vy1 = (unsigned)(y0 + 1) < 64u;
    w00 = (vx0 && vy0) ? w00 : 0.f;
    w10 = (vx1 && vy0) ? w10 : 0.f;
    w01 = (vx0 && vy1) ? w01 : 0.f;
    w11 = (vx1 && vy1) ? w11 : 0.f;
    int xc0 = min(max(x0, 0), 63), xc1 = min(max(x0 + 1, 0), 63);
    int yc0 = min(max(y0, 0), 63), yc1 = min(max(y0 + 1, 0), 63);
    int i00 = yc0 * 64 + xc0, i10 = yc0 * 64 + xc1;
    int i01 = yc1 * 64 + xc0, i11 = yc1 * 64 + xc1;

    const float* vb0 = g_value_t + ((size_t)(b * 3 + 0) * HW) * 256 + head * 32 + lane;
    const float* vb1 = vb0 + (size_t)HW * 256;
    const float* vb2 = vb1 + (size_t)HW * 256;

    float acc = 0.f;
    #pragma unroll
    for (int j = 0; j < 12; j++) {
        const float* vb = (j < 4) ? vb0 : (j < 8 ? vb1 : vb2);
        float u00 = __shfl_sync(FULL, w00, j);
        float u10 = __shfl_sync(FULL, w10, j);
        float u01 = __shfl_sync(FULL, w01, j);
        float u11 = __shfl_sync(FULL, w11, j);
        int   k00 = __shfl_sync(FULL, i00, j);
        int   k10 = __shfl_sync(FULL, i10, j);
        int   k01 = __shfl_sync(FULL, i01, j);
        int   k11 = __shfl_sync(FULL, i11, j);
        if (u00 != 0.f) acc += u00 * vb[(size_t)k00 * 256];
        if (u10 != 0.f) acc += u10 * vb[(size_t)k10 * 256];
        if (u01 != 0.f) acc += u01 * vb[(size_t)k01 * 256];
        if (u11 != 0.f) acc += u11 * vb[(size_t)k11 * 256];
    }

    __nv_bfloat16 h = __float2bfloat16(acc);
    size_t o = tok * 256 + head * 32 + lane;
    g_samp_hi[o] = h;
    g_samp_lo[o] = __float2bfloat16(acc - __bfloat162float(h));
}

// ---------------- launcher ----------------------------------------------------------
extern "C" void kernel_launch(void* const* d_in, const int* in_sizes, int n_in,
                              void* d_out, int out_size)
{
    const float* query   = (const float*)d_in[0];
    const float* refp    = (const float*)d_in[1];
    const float* flat    = (const float*)d_in[2];
    const float* w_value = (const float*)d_in[6];
    const float* b_value = (const float*)d_in[7];
    const float* w_off   = (const float*)d_in[8];
    const float* b_off   = (const float*)d_in[9];
    const float* w_attn  = (const float*)d_in[10];
    const float* b_attn  = (const float*)d_in[11];
    const float* w_out   = (const float*)d_in[12];
    const float* b_out   = (const float*)d_in[13];

    __nv_bfloat16 *q_hi, *q_lo, *f_hi, *f_lo;
    cudaGetSymbolAddress((void**)&q_hi, g_q_hi);
    cudaGetSymbolAddress((void**)&q_lo, g_q_lo);
    cudaGetSymbolAddress((void**)&f_hi, g_flat_hi);
    cudaGetSymbolAddress((void**)&f_lo, g_flat_lo);

    cudaFuncSetAttribute(conv_pair, cudaFuncAttributeMaxDynamicSharedMemorySize, SMEM_BYTES);
    cudaFuncSetAttribute(conv_out,  cudaFuncAttributeMaxDynamicSharedMemorySize, SMEM_BYTES);

    chlast_split<<<dim3(128, 8, 12), dim3(32, 8)>>>(flat, f_hi, f_lo, 256);
    chlast_split<<<dim3(128, 24, 4), dim3(32, 8)>>>(query, q_hi, q_lo, 768);
    wprep<<<(WN0 + WN1 + WN2 + WN3 + 288 + 255) / 256, 256>>>(w_value, w_off, w_attn, w_out, b_off, b_attn);

    // launch 3 (ncu window): merged value + off/attn convs
    conv_pair<<<1152, 256, SMEM_BYTES>>>(b_value);

    // launch 4: deformable attention sampling (lane-parallel v2)
    msda_kernel<<<(4 * HW * 8) / 8, 256>>>(refp);

    // launch 5: output conv -> NCHW d_out
    conv_out<<<dim3(32, 2, 4), 256, SMEM_BYTES>>>(b_out, (float*)d_out);
}

// round 12
// speedup vs baseline: 1.3797x; 1.3241x over previous
#include <cuda_runtime.h>
#include <cuda_fp16.h>
#include <cstdint>
#include <math.h>

#define HW 4096
#define CPA_B 80                    // A smem row stride (bytes), 16B-aligned for ldmatrix
#define CPB_B 80                    // B smem row stride (bytes)
#define A_POS (4 * 66)              // halo positions per chunk tile
#define A_HALF_B (A_POS * CPA_B)    // bytes per hi/lo half
#define B_SLOT_B (128 * CPB_B)      // slot: up to 128 n rows, single (hi-only) weights
#define SMEM_BYTES (2 * A_HALF_B + 3 * B_SLOT_B)   // 72960

// ---------------- device scratch ----------------
__device__ __half g_q_hi   [4u * 4096u * 768u];
__device__ __half g_q_lo   [4u * 4096u * 768u];
__device__ __half g_flat_hi[12u * 4096u * 256u];
__device__ __half g_flat_lo[12u * 4096u * 256u];
__device__ __half g_samp_hi[4u * 4096u * 256u];
__device__ __half g_samp_lo[4u * 4096u * 256u];
__device__ float g_value_t[12u * 4096u * 256u];
__device__ float g_oa_t   [4u * 4096u * 288u];        // merged off(0:192)+attn(192:288), token-major
__device__ float g_boa    [288];
__device__ __half g_wv [9u * 256u * 256u];
__device__ __half g_woa[9u * 288u * 768u];
__device__ __half g_wu [9u * 256u * 256u];

// ---------------- helpers ----------------
__device__ __forceinline__ void mma16816(float* c, const unsigned* a, unsigned b0, unsigned b1)
{
    asm volatile("mma.sync.aligned.m16n8k16.row.col.f32.f16.f16.f32 "
        "{%0,%1,%2,%3}, {%4,%5,%6,%7}, {%8,%9}, {%0,%1,%2,%3};"
        : "+f"(c[0]), "+f"(c[1]), "+f"(c[2]), "+f"(c[3])
        : "r"(a[0]), "r"(a[1]), "r"(a[2]), "r"(a[3]), "r"(b0), "r"(b1));
}

__device__ __forceinline__ void cp16(unsigned daddr, const void* src, int srcsz)
{
    asm volatile("cp.async.cg.shared.global [%0], [%1], 16, %2;\n"
                 :: "r"(daddr), "l"(src), "r"(srcsz));
}

__device__ __forceinline__ void ldsm4(unsigned* d, unsigned saddr)
{
    asm volatile("ldmatrix.sync.aligned.m8n8.x4.shared.b16 {%0,%1,%2,%3}, [%4];"
        : "=r"(d[0]), "=r"(d[1]), "=r"(d[2]), "=r"(d[3]) : "r"(saddr));
}

// ---------------- conversion kernels ----------------
__global__ void chlast_split(const float* __restrict__ in, __half* __restrict__ hi,
                             __half* __restrict__ lo, int C)
{
    __shared__ float t[32][33];
    int img = blockIdx.z;
    int p0 = blockIdx.x * 32, c0 = blockIdx.y * 32;
    int tx = threadIdx.x;
    for (int j = threadIdx.y; j < 32; j += 8)
        t[j][tx] = in[((size_t)img * C + c0 + j) * HW + p0 + tx];
    __syncthreads();
    for (int j = threadIdx.y; j < 32; j += 8) {
        float v = t[tx][j];
        __half h = __float2half(v);
        size_t o = ((size_t)img * HW + p0 + j) * C + c0 + tx;
        hi[o] = h;
        lo[o] = __float2half(v - __half2float(h));
    }
}

// w[co][ci][3][3] fp32 -> buf[tap][co_off+co][ci] fp16 (single, no split)
__device__ __forceinline__ void wput(const float* __restrict__ w, __half* dst,
                                     int i, int cout, int cin, int co_off, int cout_buf)
{
    int ci = i % cin; int r = i / cin; int co = r % cout; int tap = r / cout;
    float v = w[((size_t)co * cin + ci) * 9 + tap];
    dst[((size_t)tap * cout_buf + co_off + co) * cin + ci] = __float2half(v);
}

#define WN0 (9 * 256 * 256)
#define WN1 (9 * 192 * 768)
#define WN2 (9 * 96  * 768)
#define WN3 (9 * 256 * 256)
__global__ void wprep(const float* __restrict__ wv, const float* __restrict__ wo,
                      const float* __restrict__ wa, const float* __restrict__ wu,
                      const float* __restrict__ bo, const float* __restrict__ ba)
{
    int i = blockIdx.x * 256 + threadIdx.x;
    if (i < WN0) wput(wv, g_wv, i, 256, 256, 0, 256);
    else if (i < WN0 + WN1) wput(wo, g_woa, i - WN0, 192, 768, 0, 288);
    else if (i < WN0 + WN1 + WN2) wput(wa, g_woa, i - WN0 - WN1, 96, 768, 192, 288);
    else if (i < WN0 + WN1 + WN2 + WN3) wput(wu, g_wu, i - WN0 - WN1 - WN2, 256, 256, 0, 256);
    else if (i < WN0 + WN1 + WN2 + WN3 + 288) {
        int j = i - (WN0 + WN1 + WN2 + WN3);
        g_boa[j] = j < 192 ? bo[j] : ba[j - 192];
    }
}

// ---------------- tensor-core implicit-GEMM 3x3 conv body ----------------
// fp16 2-term: A split hi/lo, B single fp16. 4 MMAs per (ks, np) tile (was 6).
template<int CIN, int NTILE, bool TMAJOR>
__device__ __forceinline__ void conv_body(
         int bx, int by, int img,
         const __half* __restrict__ in_hi, const __half* __restrict__ in_lo,
         const __half* __restrict__ wt, const float* __restrict__ bias,
         float* __restrict__ out, int cout_total)
{
    extern __shared__ unsigned char smem_raw[];
    const unsigned sm_base = (unsigned)__cvta_generic_to_shared(smem_raw);
    const unsigned sA  = sm_base;                     // A hi then lo
    const unsigned sBb = sm_base + 2 * A_HALF_B;      // 3 slots (single hi)

    const int tid = threadIdx.x;
    const int lane = tid & 31, warp = tid >> 5;
    const int gid = lane >> 2, tig = lane & 3;
    const int jj = lane >> 3, rr = lane & 7;
    const int warpM = warp & 3, warpN = warp >> 2;

    constexpr int NA = NTILE / 16;
    constexpr int NWARP = NTILE / 2;

    const int Mbase = bx * 128;
    const int Nbase = by * NTILE;
    const int y0    = bx * 2;

    const int NTAP_TOT = (CIN / 32) * 9;

    float acc[2][NA][4];
    #pragma unroll
    for (int ma = 0; ma < 2; ma++)
        #pragma unroll
        for (int na = 0; na < NA; na++)
            #pragma unroll
            for (int q = 0; q < 4; q++) acc[ma][na][q] = 0.f;

    auto issue_b = [&](int g) {
        if (g < NTAP_TOT) {
            int cbb = (g / 9) * 32;
            int tp  = g % 9;
            int slot = g % 3;
            #pragma unroll 1
            for (int i = tid; i < NTILE * 4; i += 256) {
                int n = i >> 2, seg = i & 3;
                size_t gsrc = ((size_t)(tp * cout_total + Nbase + n)) * CIN + cbb + seg * 8;
                cp16(sBb + (unsigned)((slot * 128 + n) * CPB_B + seg * 16), wt + gsrc, 16);
            }
        }
        asm volatile("cp.async.commit_group;\n" ::);
    };

    issue_b(0);
    issue_b(1);

    int g = 0;
    #pragma unroll 1
    for (int cb = 0; cb < CIN; cb += 32) {
        __syncthreads();

        #pragma unroll 1
        for (int i = tid; i < A_POS * 8; i += 256) {
            int pos = i >> 3, sub = i & 7;
            int hf = sub >> 2, seg = sub & 3;
            int ry = pos / 66, col = pos % 66;
            int gy = y0 - 1 + ry, gx = col - 1;
            int ok = ((unsigned)gy < 64u && (unsigned)gx < 64u) ? 16 : 0;
            int gyc = gy < 0 ? 0 : (gy > 63 ? 63 : gy);
            int gxc = gx < 0 ? 0 : (gx > 63 ? 63 : gx);
            const __half* src = (hf ? in_lo : in_hi)
                + ((size_t)(img * HW + gyc * 64 + gxc)) * CIN + cb + seg * 8;
            cp16(sA + (unsigned)(hf * A_HALF_B + pos * CPA_B + seg * 16), src, ok);
        }
        asm volatile("cp.async.commit_group;\n" ::);

        #pragma unroll 1
        for (int tap = 0; tap < 9; tap++, g++) {
            if (tap == 0) asm volatile("cp.async.wait_group 0;\n" ::);
            else          asm volatile("cp.async.wait_group 1;\n" ::);
            __syncthreads();

            const int dy = tap / 3, dx = tap - dy * 3;
            const int slot = g % 3;
            const unsigned sBh = sBb + (unsigned)(slot * 128 * CPB_B);

            #pragma unroll
            for (int ks = 0; ks < 2; ks++) {
                const int kb2 = ks * 32;
                unsigned ra_h[2][4], ra_l[2][4];
                #pragma unroll
                for (int ma = 0; ma < 2; ma++) {
                    int pixel = warpM * 32 + ma * 16 + ((jj & 1) << 3) + rr;
                    int yy = (pixel >> 6) + dy;
                    int xx = (pixel & 63) + dx;
                    unsigned aofs = (unsigned)((yy * 66 + xx) * CPA_B + kb2 + ((jj >> 1) << 4));
                    ldsm4(ra_h[ma], sA + aofs);
                    ldsm4(ra_l[ma], sA + A_HALF_B + aofs);
                }
                #pragma unroll
                for (int np = 0; np < NA / 2; np++) {
                    int n = warpN * NWARP + (np * 2 + (jj >> 1)) * 8 + rr;
                    unsigned bofs = (unsigned)(n * CPB_B + kb2 + ((jj & 1) << 4));
                    unsigned rbh[4];
                    ldsm4(rbh, sBh + bofs);
                    #pragma unroll
                    for (int ma = 0; ma < 2; ma++) {
                        mma16816(acc[ma][np * 2],     ra_h[ma], rbh[0], rbh[1]);
                        mma16816(acc[ma][np * 2],     ra_l[ma], rbh[0], rbh[1]);
                        mma16816(acc[ma][np * 2 + 1], ra_h[ma], rbh[2], rbh[3]);
                        mma16816(acc[ma][np * 2 + 1], ra_l[ma], rbh[2], rbh[3]);
                    }
                }
            }
            issue_b(g + 2);
        }
    }

    #pragma unroll
    for (int ma = 0; ma < 2; ma++) {
        int pix = Mbase + warpM * 32 + ma * 16 + gid;
        #pragma unroll
        for (int na = 0; na < NA; na++) {
            int co = Nbase + warpN * NWARP + na * 8 + tig * 2;
            float bv0 = bias[co], bv1 = bias[co + 1];
            if (TMAJOR) {
                float2* p0 = reinterpret_cast<float2*>(out + ((size_t)img * HW + pix) * cout_total + co);
                float2* p1 = reinterpret_cast<float2*>(out + ((size_t)img * HW + pix + 8) * cout_total + co);
                *p0 = make_float2(acc[ma][na][0] + bv0, acc[ma][na][1] + bv1);
                *p1 = make_float2(acc[ma][na][2] + bv0, acc[ma][na][3] + bv1);
            } else {
                out[((size_t)img * cout_total + co)     * HW + pix]     = acc[ma][na][0] + bv0;
                out[((size_t)img * cout_total + co + 1) * HW + pix]     = acc[ma][na][1] + bv1;
                out[((size_t)img * cout_total + co)     * HW + pix + 8] = acc[ma][na][2] + bv0;
                out[((size_t)img * cout_total + co + 1) * HW + pix + 8] = acc[ma][na][3] + bv1;
            }
        }
    }
}

__global__ void __launch_bounds__(256, 2)
conv_pair(const float* __restrict__ b_value)
{
    int bxg = blockIdx.x;
    if (bxg < 384) {
        int x = bxg & 31, y = (bxg >> 5) % 3, img = bxg / 96;
        conv_body<768, 96, true>(x, y, img, g_q_hi, g_q_lo, g_woa, g_boa, g_oa_t, 288);
    } else {
        int t = bxg - 384;
        int x = t & 31, y = (t >> 5) & 1, img = t >> 6;
        conv_body<256, 128, true>(x, y, img, g_flat_hi, g_flat_lo, g_wv, b_value, g_value_t, 256);
    }
}

__global__ void __launch_bounds__(256, 2)
conv_out(const float* __restrict__ b_out, float* __restrict__ out)
{
    conv_body<256, 128, false>(blockIdx.x, blockIdx.y, blockIdx.z,
                               g_samp_hi, g_samp_lo, g_wu, b_out, out, 256);
}

// ---------------- MSDA: lane-parallel softmax + bilinear setup ------------------
__global__ __launch_bounds__(256)
void msda_kernel(const float* __restrict__ refp)
{
    const unsigned FULL = 0xFFFFFFFFu;
    int gw = blockIdx.x * 8 + (threadIdx.x >> 5);
    int lane = threadIdx.x & 31;
    int head = gw & 7;
    int pix  = (gw >> 3) & 4095;
    int b    = gw >> 15;

    size_t tok = (size_t)b * HW + pix;
    const float* op = g_oa_t + tok * 288;

    float lg = (lane < 12) ? op[192 + head * 12 + lane] : -1e30f;
    float mx = lg;
    #pragma unroll
    for (int s = 16; s > 0; s >>= 1) mx = fmaxf(mx, __shfl_xor_sync(FULL, mx, s));
    float e = (lane < 12) ? __expf(lg - mx) : 0.f;
    float den = e;
    #pragma unroll
    for (int s = 16; s > 0; s >>= 1) den += __shfl_xor_sync(FULL, den, s);
    float aw = e / den;

    float offv = (lane < 24) ? op[head * 24 + lane] : 0.f;
    float refv = (lane < 6) ? refp[tok * 6 + lane] : 0.f;

    int lsel = (lane >> 2) * 2;
    float rx = __shfl_sync(FULL, refv, lsel);
    float ry = __shfl_sync(FULL, refv, lsel + 1);
    float ox = __shfl_sync(FULL, offv, lane * 2 < 32 ? lane * 2 : 0);
    float oy = __shfl_sync(FULL, offv, lane * 2 + 1 < 32 ? lane * 2 + 1 : 0);
    float xf = rx * 64.f + ox - 0.5f;
    float yf = ry * 64.f + oy - 0.5f;
    float x0f = floorf(xf), y0f = floorf(yf);
    int x0 = (int)x0f, y0 = (int)y0f;
    float lx = xf - x0f, ly = yf - y0f;
    float w00 = (1.f - lx) * (1.f - ly) * aw;
    float w10 = lx * (1.f - ly) * aw;
    float w01 = (1.f - lx) * ly * aw;
    float w11 = lx * ly * aw;
    bool vx0 = (unsigned)x0 < 64u, vx1 = (unsigned)(x0 + 1) < 64u;
    bool vy0 = (unsigned)y0 < 64u, vy1 = (unsigned)(y0 + 1) < 64u;
    w00 = (vx0 && vy0) ? w00 : 0.f;
    w10 = (vx1 && vy0) ? w10 : 0.f;
    w01 = (vx0 && vy1) ? w01 : 0.f;
    w11 = (vx1 && vy1) ? w11 : 0.f;
    int xc0 = min(max(x0, 0), 63), xc1 = min(max(x0 + 1, 0), 63);
    int yc0 = min(max(y0, 0), 63), yc1 = min(max(y0 + 1, 0), 63);
    int i00 = yc0 * 64 + xc0, i10 = yc0 * 64 + xc1;
    int i01 = yc1 * 64 + xc0, i11 = yc1 * 64 + xc1;

    const float* vb0 = g_value_t + ((size_t)(b * 3 + 0) * HW) * 256 + head * 32 + lane;
    const float* vb1 = vb0 + (size_t)HW * 256;
    const float* vb2 = vb1 + (size_t)HW * 256;

    float acc = 0.f;
    #pragma unroll
    for (int j = 0; j < 12; j++) {
        const float* vb = (j < 4) ? vb0 : (j < 8 ? vb1 : vb2);
        float u00 = __shfl_sync(FULL, w00, j);
        float u10 = __shfl_sync(FULL, w10, j);
        float u01 = __shfl_sync(FULL, w01, j);
        float u11 = __shfl_sync(FULL, w11, j);
        int   k00 = __shfl_sync(FULL, i00, j);
        int   k10 = __shfl_sync(FULL, i10, j);
        int   k01 = __shfl_sync(FULL, i01, j);
        int   k11 = __shfl_sync(FULL, i11, j);
        if (u00 != 0.f) acc += u00 * vb[(size_t)k00 * 256];
        if (u10 != 0.f) acc += u10 * vb[(size_t)k10 * 256];
        if (u01 != 0.f) acc += u01 * vb[(size_t)k01 * 256];
        if (u11 != 0.f) acc += u11 * vb[(size_t)k11 * 256];
    }

    __half h = __float2half(acc);
    size_t o = tok * 256 + head * 32 + lane;
    g_samp_hi[o] = h;
    g_samp_lo[o] = __float2half(acc - __half2float(h));
}

// ---------------- launcher ----------------------------------------------------------
extern "C" void kernel_launch(void* const* d_in, const int* in_sizes, int n_in,
                              void* d_out, int out_size)
{
    const float* query   = (const float*)d_in[0];
    const float* refp    = (const float*)d_in[1];
    const float* flat    = (const float*)d_in[2];
    const float* w_value = (const float*)d_in[6];
    const float* b_value = (const float*)d_in[7];
    const float* w_off   = (const float*)d_in[8];
    const float* b_off   = (const float*)d_in[9];
    const float* w_attn  = (const float*)d_in[10];
    const float* b_attn  = (const float*)d_in[11];
    const float* w_out   = (const float*)d_in[12];
    const float* b_out   = (const float*)d_in[13];

    __half *q_hi, *q_lo, *f_hi, *f_lo;
    cudaGetSymbolAddress((void**)&q_hi, g_q_hi);
    cudaGetSymbolAddress((void**)&q_lo, g_q_lo);
    cudaGetSymbolAddress((void**)&f_hi, g_flat_hi);
    cudaGetSymbolAddress((void**)&f_lo, g_flat_lo);

    cudaFuncSetAttribute(conv_pair, cudaFuncAttributeMaxDynamicSharedMemorySize, SMEM_BYTES);
    cudaFuncSetAttribute(conv_out,  cudaFuncAttributeMaxDynamicSharedMemorySize, SMEM_BYTES);

    chlast_split<<<dim3(128, 8, 12), dim3(32, 8)>>>(flat, f_hi, f_lo, 256);
    chlast_split<<<dim3(128, 24, 4), dim3(32, 8)>>>(query, q_hi, q_lo, 768);
    wprep<<<(WN0 + WN1 + WN2 + WN3 + 288 + 255) / 256, 256>>>(w_value, w_off, w_attn, w_out, b_off, b_attn);

    // launch 3 (ncu window): merged value + off/attn convs (fp16 2-term)
    conv_pair<<<1152, 256, SMEM_BYTES>>>(b_value);

    // launch 4: deformable attention sampling
    msda_kernel<<<(4 * HW * 8) / 8, 256>>>(refp);

    // launch 5: output conv -> NCHW d_out
    conv_out<<<dim3(32, 2, 4), 256, SMEM_BYTES>>>(b_out, (float*)d_out);
}